// round 4
// baseline (speedup 1.0000x reference)
#include <cuda_runtime.h>

// Depthwise cross-correlation (XLA conv semantics, no kernel flip):
//   out[ch, ho, wo] = sum_{ky<7, kx<7} x[ch, ho+ky, wo+kx] * z[ch, ky, kx]
// x: [32768, 31, 31], z: [32768, 7, 7], out: [32768, 25, 25], all fp32.
//
// Mapping: 1 CTA (128 thr) = 2 channels; each channel served by 2 warps,
// each warp computing 13 output rows (halves overlap at ho=12 with identical
// arithmetic). 25 active lanes per warp, one output column each.
// FMA2 parity trick: even/odd output columns use parity-shifted zero-padded
// tap pairs so every 7-tap row dot product = 4 aligned LDS.64 + 4 fma.f32x2.
// ky is processed in 4 phases so only 8 tap-pairs are register-live at once.

#define HX 31
#define WX 31
#define HZ 7
#define WZ 7
#define HO 25
#define WO 25
#define HOT 13          // output rows per warp
#define NCH (128 * 256)

__device__ __forceinline__ void fma2(unsigned long long &d,
                                     unsigned long long a,
                                     unsigned long long b) {
    // packed f32x2 FMA (sm_100+): d.lo += a.lo*b.lo; d.hi += a.hi*b.hi
    asm("fma.rn.f32x2 %0, %1, %2, %0;" : "+l"(d) : "l"(a), "l"(b));
}

__device__ __forceinline__ unsigned long long lds2(const float* p) {
    return *reinterpret_cast<const unsigned long long*>(p);
}

// One ky-phase: taps KA..KA+NK-1 live in registers (NK<=2 -> <=16 regs),
// walk the x rows this phase touches, accumulate into acc[0..HOT-1].
template <int KA, int NK>
__device__ __forceinline__ void phase(const float (*__restrict__ sxr)[32],
                                      const float (*__restrict__ skp)[8],
                                      int ho0, int x0,
                                      unsigned long long acc[HOT]) {
    unsigned long long kk[NK][4];
#pragma unroll
    for (int q = 0; q < NK; q++)
#pragma unroll
        for (int j = 0; j < 4; j++)
            kk[q][j] = lds2(&skp[KA + q][2 * j]);

    constexpr int NR = HOT + NK - 1;
#pragma unroll
    for (int rr = 0; rr < NR; rr++) {
        const float* row = &sxr[ho0 + KA + rr][x0];
        const unsigned long long p0 = lds2(row + 0);
        const unsigned long long p1 = lds2(row + 2);
        const unsigned long long p2 = lds2(row + 4);
        const unsigned long long p3 = lds2(row + 6);
        if (rr < HOT) {               // ky = KA contributes to acc[rr]
            fma2(acc[rr], p0, kk[0][0]);
            fma2(acc[rr], p1, kk[0][1]);
            fma2(acc[rr], p2, kk[0][2]);
            fma2(acc[rr], p3, kk[0][3]);
        }
        if (NK == 2 && rr >= 1) {     // ky = KA+1 contributes to acc[rr-1]
            fma2(acc[rr - 1], p0, kk[1][0]);
            fma2(acc[rr - 1], p1, kk[1][1]);
            fma2(acc[rr - 1], p2, kk[1][2]);
            fma2(acc[rr - 1], p3, kk[1][3]);
        }
    }
}

__global__ void __launch_bounds__(128, 8)
dwxcorr_v3(const float* __restrict__ zf,
           const float* __restrict__ xf,
           float* __restrict__ out) {
    __shared__ __align__(16) float sx[2][HX][32];      // [ch][row][31 + zero pad]
    __shared__ __align__(16) float sk[2][2][HZ][8];    // [ch][parity][ky][padded taps]

    const int tid  = threadIdx.x;
    const int warp = tid >> 5;
    const int lane = tid & 31;
    const int g    = warp >> 1;        // channel within CTA (0/1)
    const int half = warp & 1;         // output-row half
    const int base = blockIdx.x * 2;

    // ---- stage 2 channels of x (coalesced) ----
    for (int i = tid; i < 2 * HX * WX; i += 128) {
        int gg  = i / (HX * WX);
        int rem = i - gg * (HX * WX);
        int r   = rem / WX;
        int c   = rem - r * WX;
        sx[gg][r][c] = xf[(long long)(base + gg) * (HX * WX) + rem];
    }
    if (tid < 2 * HX) sx[tid / HX][tid % HX][WX] = 0.0f;   // zero pad col 31

    // ---- stage taps: two parity-shifted zero-padded copies per channel ----
    // even copy: [k0 k1 k2 k3 k4 k5 k6 0]   odd copy: [0 k0 k1 k2 k3 k4 k5 k6]
    for (int i = tid; i < 2 * 2 * HZ * 8; i += 128) {      // 224 values
        int gg   = i / (2 * HZ * 8);
        int rem  = i - gg * (2 * HZ * 8);
        int par  = rem / (HZ * 8);
        int rem2 = rem - par * (HZ * 8);
        int ky   = rem2 >> 3;
        int j    = rem2 & 7;
        const float* zc = zf + (long long)(base + gg) * (HZ * WZ);
        sk[gg][par][ky][j] = (par == 0) ? ((j < WZ) ? zc[ky * WZ + j] : 0.0f)
                                        : ((j >= 1) ? zc[ky * WZ + j - 1] : 0.0f);
    }
    __syncthreads();

    if (lane >= WO) return;            // 25 active lanes per warp

    const int wo  = lane;
    const int par = wo & 1;
    const int x0  = wo & ~1;           // even-aligned pair base
    const int ho0 = half * (HO - HOT); // 0 or 12

    unsigned long long acc[HOT];
#pragma unroll
    for (int i = 0; i < HOT; i++) acc[i] = 0ULL;

    const float (*__restrict__ sxr)[32] = sx[g];
    const float (*__restrict__ skp)[8]  = sk[g][par];

    phase<0, 2>(sxr, skp, ho0, x0, acc);
    phase<2, 2>(sxr, skp, ho0, x0, acc);
    phase<4, 2>(sxr, skp, ho0, x0, acc);
    phase<6, 1>(sxr, skp, ho0, x0, acc);

    float* __restrict__ och =
        out + (long long)(base + g) * (HO * WO) + (long long)ho0 * WO + wo;
#pragma unroll
    for (int i = 0; i < HOT; i++) {
        float2 v = *reinterpret_cast<float2*>(&acc[i]);
        och[i * WO] = v.x + v.y;
    }
}

extern "C" void kernel_launch(void* const* d_in, const int* in_sizes, int n_in,
                              void* d_out, int out_size) {
    // metadata order: z_f [128,256,7,7] then x_f [128,256,31,31]
    const float* z = (const float*)d_in[0];
    const float* x = (const float*)d_in[1];
    if (n_in >= 2 && in_sizes[0] > in_sizes[1]) {   // defensive: z is the small one
        const float* t = z; z = x; x = t;
    }
    float* o = (float*)d_out;

    dim3 grid(NCH / 2);   // 16384 CTAs, 2 channels each
    dim3 block(128);
    dwxcorr_v3<<<grid, block>>>(z, x, o);
}

// round 6
// speedup vs baseline: 2.1095x; 2.1095x over previous
#include <cuda_runtime.h>

// Depthwise cross-correlation (XLA conv semantics, no kernel flip):
//   out[ch, ho, wo] = sum_{ky<7, kx<7} x[ch, ho+ky, wo+kx] * z[ch, ky, kx]
// x: [32768, 31, 31], z: [32768, 7, 7], out: [32768, 25, 25], all fp32.
//
// Mapping (as in the 117us best): 1 warp = 1 channel, 4 channels / 128-thr CTA,
// 25 active lanes, one output column each, 25 packed-f32x2 row accumulators.
// Register diet vs that version: the zero-containing tap pair of each parity is
// replaced by a scalar FFMA whose x operand sits at a parity-uniform column,
// so per ky we do 3 fma.f32x2 + 1 scalar fma (same FMA-pipe cycles), taps drop
// from 28 pairs (56 regs) to 21 pairs + 7 scalars (49 regs). Target: 5 CTAs/SM.

#define HX 31
#define WX 31
#define HZ 7
#define WZ 7
#define HO 25
#define WO 25
#define XPAD 32
#define CH_PER_CTA 4
#define NCH (128 * 256)

__device__ __forceinline__ void fma2(float2 &d, unsigned long long a,
                                     unsigned long long b) {
    // packed f32x2 FMA (sm_100+): d.x += a.lo*b.lo; d.y += a.hi*b.hi
    unsigned long long dd = *reinterpret_cast<unsigned long long*>(&d);
    asm("fma.rn.f32x2 %0, %1, %2, %0;" : "+l"(dd) : "l"(a), "l"(b));
    d = *reinterpret_cast<float2*>(&dd);
}

__device__ __forceinline__ unsigned long long lds2(const float* p) {
    return *reinterpret_cast<const unsigned long long*>(p);
}

__global__ void __launch_bounds__(128, 5)
dwxcorr_v4(const float* __restrict__ zf,
           const float* __restrict__ xf,
           float* __restrict__ out) {
    __shared__ __align__(16) float sx[CH_PER_CTA][HX][XPAD];
    __shared__ __align__(16) float sk[CH_PER_CTA][2][HZ][8];

    const int tid  = threadIdx.x;
    const int warp = tid >> 5;
    const int lane = tid & 31;
    const int ch   = blockIdx.x * CH_PER_CTA + warp;

    const float* __restrict__ xch = xf + (long long)ch * (HX * WX);
    const float* __restrict__ zch = zf + (long long)ch * (HZ * WZ);

    // ---- stage x tile (per-warp, coalesced; col 31 never read -> no pad) ----
    for (int i = lane; i < HX * WX; i += 32) {
        int r = i / WX;
        int c = i - r * WX;
        sx[warp][r][c] = xch[i];
    }

    // ---- stage taps: two parity-shifted copies ----
    // copy0: [k0 k1 k2 k3 k4 k5 k6 0]   copy1: [0 k0 k1 k2 k3 k4 k5 k6]
    for (int i = lane; i < HZ * 8; i += 32) {
        int ky = i >> 3;
        int j  = i & 7;
        sk[warp][0][ky][j] = (j < WZ) ? zch[ky * WZ + j] : 0.0f;
        sk[warp][1][ky][j] = (j >= 1) ? zch[ky * WZ + (j - 1)] : 0.0f;
    }
    __syncwarp();

    if (lane >= WO) return;                 // 25 active lanes

    const int wo  = lane;
    const int par = wo & 1;
    const int B   = (wo & ~1) + 2 * par;    // pair-load base: even wo -> wo, odd -> wo+1
    const int S   = wo + 6 * (1 - par);     // scalar x column: even -> wo+6, odd -> wo

    // 21 tap pairs + 7 scalar taps -> registers
    // even lanes: pairs {k0,k1}{k2,k3}{k4,k5} (copy0 offs 0,2,4), scalar k6 (copy0[6])
    // odd  lanes: pairs {k1,k2}{k3,k4}{k5,k6} (copy1 offs 2,4,6), scalar k0 (copy1[1])
    unsigned long long kp[HZ][3];
    float ks[HZ];
    const int pofs = 2 * par;               // pair base offset within parity copy
    const int sofs = 6 - 5 * par;           // scalar tap offset within parity copy
#pragma unroll
    for (int ky = 0; ky < HZ; ky++) {
#pragma unroll
        for (int j = 0; j < 3; j++)
            kp[ky][j] = lds2(&sk[warp][par][ky][pofs + 2 * j]);
        ks[ky] = sk[warp][par][ky][sofs];
    }

    float2 acc[HO];
#pragma unroll
    for (int i = 0; i < HO; i++) acc[i] = make_float2(0.0f, 0.0f);

    const float* __restrict__ sxw = &sx[warp][0][0];

#pragma unroll
    for (int r = 0; r < HX; r++) {
        const float* row = sxw + r * XPAD;
        const unsigned long long p0 = lds2(row + B);
        const unsigned long long p1 = lds2(row + B + 2);
        const unsigned long long p2 = lds2(row + B + 4);
        const float xs = row[S];
#pragma unroll
        for (int ky = 0; ky < HZ; ky++) {
            const int ho = r - ky;
            if (ho >= 0 && ho < HO) {
                fma2(acc[ho], p0, kp[ky][0]);
                fma2(acc[ho], p1, kp[ky][1]);
                fma2(acc[ho], p2, kp[ky][2]);
                acc[ho].x = fmaf(xs, ks[ky], acc[ho].x);  // lo+hi commute
            }
        }
    }

    float* __restrict__ och = out + (long long)ch * (HO * WO) + wo;
#pragma unroll
    for (int ho = 0; ho < HO; ho++)
        och[ho * WO] = acc[ho].x + acc[ho].y;
}

extern "C" void kernel_launch(void* const* d_in, const int* in_sizes, int n_in,
                              void* d_out, int out_size) {
    // metadata order: z_f [128,256,7,7] then x_f [128,256,31,31]
    const float* z = (const float*)d_in[0];
    const float* x = (const float*)d_in[1];
    if (n_in >= 2 && in_sizes[0] > in_sizes[1]) {   // defensive: z is the small one
        const float* t = z; z = x; x = t;
    }
    float* o = (float*)d_out;

    dim3 grid(NCH / CH_PER_CTA);
    dim3 block(128);
    dwxcorr_v4<<<grid, block>>>(z, x, o);
}

// round 7
// speedup vs baseline: 3.5826x; 1.6983x over previous
#include <cuda_runtime.h>
#include <cstdint>

// Depthwise cross-correlation (XLA conv semantics, no kernel flip):
//   out[ch, ho, wo] = sum_{ky<7, kx<7} x[ch, ho+ky, wo+kx] * z[ch, ky, kx]
// x: [32768, 31, 31], z: [32768, 7, 7], out: [32768, 25, 25], all fp32.
//
// v5 = v4 (105us) with the prologue fixed: x is staged via fully-unrolled
// cp.async (LDGSTS) with MLP=31 instead of a rolled LDG->STS loop with MLP=1
// that serialized ~31 DRAM round-trips (~20K cyc) per CTA.
//
// Mapping: 1 warp = 1 channel, 4 channels / 128-thr CTA, 25 active lanes,
// one output column each, 25 packed-f32x2 row accumulators.
// Parity trick: per ky, 3 aligned LDS.64 pair loads + 1 scalar LDS.32 feed
// 3 fma.f32x2 + 1 scalar fma.

#define HX 31
#define WX 31
#define HZ 7
#define WZ 7
#define HO 25
#define WO 25
#define XPAD 32
#define CH_PER_CTA 4
#define NCH (128 * 256)

__device__ __forceinline__ void fma2(float2 &d, unsigned long long a,
                                     unsigned long long b) {
    // packed f32x2 FMA (sm_100+): d.x += a.lo*b.lo; d.y += a.hi*b.hi
    unsigned long long dd = *reinterpret_cast<unsigned long long*>(&d);
    asm("fma.rn.f32x2 %0, %1, %2, %0;" : "+l"(dd) : "l"(a), "l"(b));
    d = *reinterpret_cast<float2*>(&dd);
}

__device__ __forceinline__ unsigned long long lds2(const float* p) {
    return *reinterpret_cast<const unsigned long long*>(p);
}

__device__ __forceinline__ uint32_t smem_u32(const void* p) {
    uint32_t a;
    asm("{ .reg .u64 t; cvta.to.shared.u64 t, %1; cvt.u32.u64 %0, t; }"
        : "=r"(a) : "l"(p));
    return a;
}

__device__ __forceinline__ void cp4(uint32_t dst, const float* src) {
    asm volatile("cp.async.ca.shared.global [%0], [%1], 4;"
                 :: "r"(dst), "l"(src));
}

__global__ void __launch_bounds__(128, 5)
dwxcorr_v5(const float* __restrict__ zf,
           const float* __restrict__ xf,
           float* __restrict__ out) {
    __shared__ __align__(16) float sx[CH_PER_CTA][HX][XPAD];
    __shared__ __align__(16) float sk[CH_PER_CTA][2][HZ][8];

    const int tid  = threadIdx.x;
    const int warp = tid >> 5;
    const int lane = tid & 31;
    const int ch   = blockIdx.x * CH_PER_CTA + warp;

    const float* __restrict__ xch = xf + (long long)ch * (HX * WX);
    const float* __restrict__ zch = zf + (long long)ch * (HZ * WZ);

    // ---- taps: 2 LDG per lane, in flight alongside the async copies ----
    float z0 = 0.0f, z1 = 0.0f;
    if (lane < 25)      z0 = zch[lane];
    if (lane + 25 < 49) z1 = zch[lane + 25];
    // (lane 24: z1 = zch[49]? no: 24+25=49 -> guarded out. lanes 0..23 load 25..48)

    // ---- stage x via fully-unrolled cp.async: MLP = 31, no index division ----
    {
        const uint32_t sbase = smem_u32(&sx[warp][0][0]);
#pragma unroll
        for (int r = 0; r < HX; r++) {
            if (lane < WX)
                cp4(sbase + (uint32_t)(r * XPAD + lane) * 4u,
                    xch + r * WX + lane);
        }
        asm volatile("cp.async.commit_group;" ::: "memory");
    }

    // ---- build the two parity-shifted tap copies while copies fly ----
    // copy0: [k0 k1 k2 k3 k4 k5 k6 0]   copy1: [0 k0 k1 k2 k3 k4 k5 k6]
    if (lane < 25) {                       // z[lane] = z[ky*7 + j]
        int ky = lane / WZ, j = lane - ky * WZ;
        sk[warp][0][ky][j]     = z0;
        sk[warp][1][ky][j + 1] = z0;
    }
    if (lane < 24) {                       // z[lane+25]
        int i2 = lane + 25;
        int ky = i2 / WZ, j = i2 - ky * WZ;
        sk[warp][0][ky][j]     = z1;
        sk[warp][1][ky][j + 1] = z1;
    }
    if (lane < HZ) {                       // zero pads
        sk[warp][0][lane][7] = 0.0f;
        sk[warp][1][lane][0] = 0.0f;
    }

    asm volatile("cp.async.wait_group 0;" ::: "memory");
    __syncthreads();                        // publish async copies + tap STS

    if (lane >= WO) return;                 // 25 active lanes

    const int wo  = lane;
    const int par = wo & 1;
    const int B   = (wo & ~1) + 2 * par;    // pair-load base (8B aligned)
    const int S   = wo + 6 * (1 - par);     // scalar x column
    const int pofs = 2 * par;               // pair offset within parity copy
    const int sofs = 6 - 5 * par;           // scalar tap offset

    // 21 tap pairs + 7 scalars -> registers (49 regs)
    unsigned long long kp[HZ][3];
    float ks[HZ];
#pragma unroll
    for (int ky = 0; ky < HZ; ky++) {
#pragma unroll
        for (int j = 0; j < 3; j++)
            kp[ky][j] = lds2(&sk[warp][par][ky][pofs + 2 * j]);
        ks[ky] = sk[warp][par][ky][sofs];
    }

    float2 acc[HO];
#pragma unroll
    for (int i = 0; i < HO; i++) acc[i] = make_float2(0.0f, 0.0f);

    const float* __restrict__ sxw = &sx[warp][0][0];

#pragma unroll
    for (int r = 0; r < HX; r++) {
        const float* row = sxw + r * XPAD;
        const unsigned long long p0 = lds2(row + B);
        const unsigned long long p1 = lds2(row + B + 2);
        const unsigned long long p2 = lds2(row + B + 4);
        const float xs = row[S];
#pragma unroll
        for (int ky = 0; ky < HZ; ky++) {
            const int ho = r - ky;
            if (ho >= 0 && ho < HO) {
                fma2(acc[ho], p0, kp[ky][0]);
                fma2(acc[ho], p1, kp[ky][1]);
                fma2(acc[ho], p2, kp[ky][2]);
                acc[ho].x = fmaf(xs, ks[ky], acc[ho].x);   // lo+hi commute
            }
        }
    }

    float* __restrict__ och = out + (long long)ch * (HO * WO) + wo;
#pragma unroll
    for (int ho = 0; ho < HO; ho++)
        och[ho * WO] = acc[ho].x + acc[ho].y;
}

extern "C" void kernel_launch(void* const* d_in, const int* in_sizes, int n_in,
                              void* d_out, int out_size) {
    // metadata order: z_f [128,256,7,7] then x_f [128,256,31,31]
    const float* z = (const float*)d_in[0];
    const float* x = (const float*)d_in[1];
    if (n_in >= 2 && in_sizes[0] > in_sizes[1]) {   // defensive: z is the small one
        const float* t = z; z = x; x = t;
    }
    float* o = (float*)d_out;

    dim3 grid(NCH / CH_PER_CTA);
    dim3 block(128);
    dwxcorr_v5<<<grid, block>>>(z, x, o);
}